// round 3
// baseline (speedup 1.0000x reference)
#include <cuda_runtime.h>
#include <math.h>

// EntropyLoss: x [R=65536, C=1024] f32 row-major.
//   n_j  = max( sqrt(sum_i x_ij^2), 1e-12 )
//   out  = -(1/R) * sum_j (1/n_j) * [ sum_i x*ln(x) - ln(n_j) * sum_i x ]
// (eps=1e-8 inside the reference log contributes <1e-6 relative error; dropped)

#define COLS 1024

// Per-column partial sums: [0]=sum x^2, [1]=sum x, [2]=sum x*ln(x)
__device__ float g_part[3][COLS];

__global__ void el_zero_kernel() {
    int i = blockIdx.x * blockDim.x + threadIdx.x;
    if (i < 3 * COLS) ((float*)g_part)[i] = 0.0f;
}

__global__ __launch_bounds__(256) void el_accum_kernel(const float* __restrict__ x, int rows) {
    const int tid     = threadIdx.x;
    const int cg      = tid & 63;     // 64 float4 column-groups per block (256 cols)
    const int slice   = tid >> 6;     // 4 row slices per block
    const int colbase = blockIdx.y * 256;
    const int g4      = (colbase >> 2) + cg;   // float4 index within a row (row has 256 float4)

    const float4* __restrict__ p = (const float4*)x;

    float s2[4] = {0.f, 0.f, 0.f, 0.f};
    float s1[4] = {0.f, 0.f, 0.f, 0.f};
    float sx[4] = {0.f, 0.f, 0.f, 0.f};

    const int rstride = gridDim.x * 4;
    #pragma unroll 4
    for (int r = blockIdx.x * 4 + slice; r < rows; r += rstride) {
        float4 v = p[(long)r * (COLS / 4) + g4];
        float vv[4] = {v.x, v.y, v.z, v.w};
        #pragma unroll
        for (int k = 0; k < 4; k++) {
            float a = vv[k];
            s2[k] = fmaf(a, a, s2[k]);
            s1[k] += a;
            // x*ln(x): at a==0 this is fmaf(0, ln(1e-37), s) == s (correct limit)
            float l = __logf(fmaxf(a, 1e-37f));
            sx[k] = fmaf(a, l, sx[k]);
        }
    }

    // Reduce the 4 row-slices within the block before touching L2 atomics:
    // cuts global atomic count 4x (-> ~909k atomics total across the grid).
    __shared__ float red[4][64 * 12];
    #pragma unroll
    for (int k = 0; k < 4; k++) {
        red[slice][cg * 12 + 0 + k] = s2[k];
        red[slice][cg * 12 + 4 + k] = s1[k];
        red[slice][cg * 12 + 8 + k] = sx[k];
    }
    __syncthreads();

    for (int i = tid; i < 64 * 12; i += 256) {
        float t = red[0][i] + red[1][i] + red[2][i] + red[3][i];
        int cg2  = i / 12;
        int comp = i % 12;
        int type = comp >> 2;     // 0: x^2, 1: x, 2: x*ln(x)
        int sub  = comp & 3;
        int col  = colbase + cg2 * 4 + sub;
        atomicAdd(&g_part[type][col], t);
    }
}

__global__ __launch_bounds__(1024) void el_final_kernel(float* __restrict__ out, int rows) {
    const int j = threadIdx.x;  // 1024 threads, one per column
    float S2 = g_part[0][j];
    float S1 = g_part[1][j];
    float SX = g_part[2][j];
    float n  = fmaxf(sqrtf(S2), 1e-12f);
    float t  = (SX - S1 * logf(n)) / n;

    __shared__ float sm[1024];
    sm[j] = t;
    __syncthreads();
    #pragma unroll
    for (int s = 512; s > 0; s >>= 1) {
        if (j < s) sm[j] += sm[j + s];
        __syncthreads();
    }
    if (j == 0) out[0] = -sm[0] / (float)rows;
}

extern "C" void kernel_launch(void* const* d_in, const int* in_sizes, int n_in,
                              void* d_out, int out_size) {
    const float* x = (const float*)d_in[0];
    int rows = in_sizes[0] / COLS;   // 65536

    el_zero_kernel<<<3, 1024>>>();

    dim3 grid(296, 4);               // 296 row-chunks x 4 column-tiles = 1184 CTAs (8/SM)
    el_accum_kernel<<<grid, 256>>>(x, rows);

    el_final_kernel<<<1, 1024>>>((float*)d_out, rows);
}